// round 2
// baseline (speedup 1.0000x reference)
#include <cuda_runtime.h>
#include <cstdint>
#include <cstddef>

#define NROWS 131072
#define NDENSE 13
#define NSPARSE 26
#define NFIELD 39
#define EMBD 16
#define HID 32
#define VOCABSZ 100000
#define EPSV 1e-5f
#define SWROWS (NSPARSE * EMBD)   // 416 sparse rows of Wl1
#define SWSTRIDE 36               // padded row stride (floats) -> conflict-free quad reads

// ---- scratch (static device globals; no allocation) ----
__device__ float g_x1[(size_t)HID * NROWS];   // column-major [HID][NROWS]
__device__ float g_rest[NROWS];
__device__ float g_S1[HID];
__device__ float g_S2[HID * HID];
__device__ float g_u[HID];
__device__ float g_c0;
__device__ float g_A2[NDENSE * HID];
__device__ float g_B2[NDENSE * HID];
__device__ float g_w1s[NDENSE];
__device__ float g_b1s[NDENSE];

// ---- packed f32x2 helpers (Blackwell) ----
typedef unsigned long long ull;
__device__ __forceinline__ ull pk2(float a, float b) {
    ull r;
    asm("mov.b64 %0, {%1, %2};" : "=l"(r)
        : "r"(__float_as_uint(a)), "r"(__float_as_uint(b)));
    return r;
}
__device__ __forceinline__ void upk2(ull v, float& a, float& b) {
    unsigned int x, y;
    asm("mov.b64 {%0, %1}, %2;" : "=r"(x), "=r"(y) : "l"(v));
    a = __uint_as_float(x); b = __uint_as_float(y);
}
__device__ __forceinline__ ull fma2(ull a, ull b, ull c) {
    ull d;
    asm("fma.rn.f32x2 %0, %1, %2, %3;" : "=l"(d) : "l"(a), "l"(b), "l"(c));
    return d;
}
__device__ __forceinline__ ull add2(ull a, ull b) {
    ull d;
    asm("add.rn.f32x2 %0, %1, %2;" : "=l"(d) : "l"(a), "l"(b));
    return d;
}

// ---- K0: fold dense projections, zero stats ----
__global__ void pre_kernel(const float* __restrict__ W1d, const float* __restrict__ b1d,
                           const float* __restrict__ W2d, const float* __restrict__ b2d,
                           const float* __restrict__ Wl1) {
    int t = threadIdx.x;
    if (t < NDENSE * HID) {
        int f = t >> 5, j = t & 31;
        float a = 0.f, b = 0.f;
        #pragma unroll
        for (int e = 0; e < EMBD; e++) {
            float w = Wl1[(f * EMBD + e) * HID + j];
            a = fmaf(W2d[f * EMBD + e], w, a);
            b = fmaf(b2d[f * EMBD + e], w, b);
        }
        g_A2[t] = a; g_B2[t] = b;
    }
    if (t < NDENSE) {
        float a = 0.f, b = 0.f;
        #pragma unroll
        for (int e = 0; e < EMBD; e++) { a += W1d[t * EMBD + e]; b += b1d[t * EMBD + e]; }
        g_w1s[t] = a; g_b1s[t] = b;
    }
    if (t < HID) g_S1[t] = 0.f;
    if (t < HID * HID) g_S2[t] = 0.f;
}

// ---- K1: fused embed + FM + deep@Wl1 — quad-cooperative (4 lanes per row) ----
__global__ __launch_bounds__(256, 3) void main_kernel(
    const float* __restrict__ Xi_dense, const int* __restrict__ Xi_sparse,
    const float* __restrict__ Xv, const float* __restrict__ bias,
    const float* __restrict__ T1, const float* __restrict__ T2,
    const float* __restrict__ W2d, const float* __restrict__ b2d,
    const float* __restrict__ Wl1, const float* __restrict__ bl1)
{
    extern __shared__ float sm[];
    float* sWl1 = sm;                              // SWROWS*SWSTRIDE = 14976
    float* sA2  = sWl1 + SWROWS * SWSTRIDE;        // 416
    float* sB2  = sA2 + NDENSE * HID;              // 416
    float* sW2  = sB2 + NDENSE * HID;              // 208
    float* sb2  = sW2 + NDENSE * EMBD;             // 208
    float* sw1  = sb2 + NDENSE * EMBD;             // 13
    float* sb1  = sw1 + NDENSE;                    // 13
    float* sbl  = sb1 + NDENSE;                    // 32

    // load sparse rows of Wl1 (global rows 208..623) with padded stride
    for (int i = threadIdx.x; i < SWROWS * HID; i += blockDim.x) {
        int r = i >> 5, c = i & 31;
        sWl1[r * SWSTRIDE + c] = Wl1[(NDENSE * EMBD + r) * HID + c];
    }
    for (int i = threadIdx.x; i < NDENSE * HID; i += blockDim.x) { sA2[i] = g_A2[i]; sB2[i] = g_B2[i]; }
    for (int i = threadIdx.x; i < NDENSE * EMBD; i += blockDim.x) { sW2[i] = W2d[i]; sb2[i] = b2d[i]; }
    if (threadIdx.x < NDENSE) { sw1[threadIdx.x] = g_w1s[threadIdx.x]; sb1[threadIdx.x] = g_b1s[threadIdx.x]; }
    if (threadIdx.x < HID) sbl[threadIdx.x] = bl1[threadIdx.x];
    __syncthreads();

    const int warp = threadIdx.x >> 5;
    const int lane = threadIdx.x & 31;
    const int quad = lane >> 2;     // 8 rows per warp
    const int ql   = lane & 3;      // e-range owner: e in [4*ql, 4*ql+4)
    const int row  = blockIdx.x * 64 + warp * 8 + quad;

    ull x1p[16];
    #pragma unroll
    for (int i = 0; i < 16; i++) x1p[i] = 0ull;
    ull s01 = 0ull, s23 = 0ull, sqp = 0ull;
    float rest = (ql == 0) ? __ldg(bias + row) : 0.f;

    const float* xvp = Xv + (size_t)row * NFIELD;
    const float* xdp = Xi_dense + (size_t)row * NDENSE;
    const int*   xsp = Xi_sparse + (size_t)row * NSPARSE;

    // ---- dense fields ----
    #pragma unroll 1
    for (int f = 0; f < NDENSE; f++) {
        float v  = __ldg(xvp + f);
        float xi = __ldg(xdp + f);
        if (ql == 0) rest = fmaf(v, fmaf(xi, sw1[f], sb1[f]), rest);
        float t0 = fmaf(xi, sW2[f * EMBD + ql * 4 + 0], sb2[f * EMBD + ql * 4 + 0]) * v;
        float t1 = fmaf(xi, sW2[f * EMBD + ql * 4 + 1], sb2[f * EMBD + ql * 4 + 1]) * v;
        float t2 = fmaf(xi, sW2[f * EMBD + ql * 4 + 2], sb2[f * EMBD + ql * 4 + 2]) * v;
        float t3 = fmaf(xi, sW2[f * EMBD + ql * 4 + 3], sb2[f * EMBD + ql * 4 + 3]) * v;
        ull p01 = pk2(t0, t1), p23 = pk2(t2, t3);
        s01 = add2(s01, p01); s23 = add2(s23, p23);
        sqp = fma2(p01, p01, sqp); sqp = fma2(p23, p23, sqp);
        if (ql == 0) {
            float xiv = xi * v;
            ull xivp = pk2(xiv, xiv);
            ull vp   = pk2(v, v);
            const ull* A = (const ull*)(sA2 + f * HID);
            const ull* B = (const ull*)(sB2 + f * HID);
            #pragma unroll
            for (int jp = 0; jp < 16; jp++) {
                x1p[jp] = fma2(xivp, A[jp], x1p[jp]);
                x1p[jp] = fma2(vp,   B[jp], x1p[jp]);
            }
        }
    }

    // ---- sparse fields (quad-cooperative 16B-per-lane gathers) ----
    #pragma unroll 2
    for (int f = 0; f < NSPARSE; f++) {
        int   idx = __ldg(xsp + f);
        float v   = __ldg(xvp + NDENSE + f);
        size_t base = ((size_t)f * VOCABSZ + (size_t)idx) * EMBD + ql * 4;
        float4 a = __ldcg((const float4*)(T1 + base));
        float4 b = __ldcg((const float4*)(T2 + base));
        rest = fmaf(v, (a.x + a.y) + (a.z + a.w), rest);
        float tv[4];
        tv[0] = b.x * v; tv[1] = b.y * v; tv[2] = b.z * v; tv[3] = b.w * v;
        ull p01 = pk2(tv[0], tv[1]), p23 = pk2(tv[2], tv[3]);
        s01 = add2(s01, p01); s23 = add2(s23, p23);
        sqp = fma2(p01, p01, sqp); sqp = fma2(p23, p23, sqp);
        const float* wb = sWl1 + (f * EMBD + ql * 4) * SWSTRIDE;
        #pragma unroll
        for (int i = 0; i < 4; i++) {
            ull te = pk2(tv[i], tv[i]);
            const ulonglong2* w = (const ulonglong2*)(wb + i * SWSTRIDE);
            #pragma unroll
            for (int q = 0; q < 8; q++) {
                ulonglong2 ww = w[q];
                x1p[2 * q]     = fma2(te, ww.x, x1p[2 * q]);
                x1p[2 * q + 1] = fma2(te, ww.y, x1p[2 * q + 1]);
            }
        }
    }

    // ---- per-lane scalar epilogue: rest + 0.5*(fm - sq), all additive over quad ----
    {
        ull f2 = fma2(s01, s01, 0ull);
        f2 = fma2(s23, s23, f2);
        float flo, fhi; upk2(f2, flo, fhi);
        float qlo, qhi; upk2(sqp, qlo, qhi);
        rest += 0.5f * ((flo + fhi) - (qlo + qhi));
    }
    // butterfly-reduce scalar part within quad
    rest += __shfl_xor_sync(0xffffffffu, rest, 1);
    rest += __shfl_xor_sync(0xffffffffu, rest, 2);
    // butterfly-reduce packed x1 partials within quad
    #pragma unroll
    for (int jp = 0; jp < 16; jp++) {
        ull v = x1p[jp];
        v = add2(v, __shfl_xor_sync(0xffffffffu, v, 1));
        v = add2(v, __shfl_xor_sync(0xffffffffu, v, 2));
        x1p[jp] = v;
    }

    if (ql == 0) {
        g_rest[row] = rest;
        #pragma unroll
        for (int jp = 0; jp < 16; jp++) {
            float lo, hi; upk2(x1p[jp], lo, hi);
            g_x1[(size_t)(2 * jp) * NROWS + row]     = lo + sbl[2 * jp];
            g_x1[(size_t)(2 * jp + 1) * NROWS + row] = hi + sbl[2 * jp + 1];
        }
    }
}

// ---- K2: S1 and full S2 = sum x1 x1^T (32x32) ----
__global__ __launch_bounds__(1024) void stats_kernel() {
    __shared__ float tile[HID][257];
    int k = threadIdx.x >> 5;
    int l = threadIdx.x & 31;
    float acc = 0.f, acc1 = 0.f;
    for (int chunk = blockIdx.x; chunk < NROWS / 256; chunk += gridDim.x) {
        int r0 = chunk * 256;
        #pragma unroll
        for (int i = 0; i < 8; i++) {
            int idx = threadIdx.x + i * 1024;
            int col = idx >> 8;
            int r = idx & 255;
            tile[col][r] = g_x1[(size_t)col * NROWS + r0 + r];
        }
        __syncthreads();
        #pragma unroll 8
        for (int r = 0; r < 256; r++) {
            float xk = tile[k][r];
            float xl = tile[l][r];
            acc = fmaf(xk, xl, acc);
            acc1 += xk;
        }
        __syncthreads();
    }
    atomicAdd(&g_S2[k * HID + l], acc);
    if (l == 0) atomicAdd(&g_S1[k], acc1);
}

// ---- K3: closed-form BN folding -> u[32], c0 (parallel, 1024 threads) ----
__global__ __launch_bounds__(1024) void fin_kernel(
        const float* __restrict__ g1, const float* __restrict__ be1,
        const float* __restrict__ Wl2, const float* __restrict__ bl2,
        const float* __restrict__ g2, const float* __restrict__ be2) {
    __shared__ float m1s[HID], a1s[HID], a2s[HID];
    __shared__ float qv[HID][HID + 1];
    __shared__ float Cm[HID][HID + 1];
    __shared__ float part[HID][HID + 1];
    const int j = threadIdx.x & 31;
    const int k = threadIdx.x >> 5;
    const float invN = 1.f / (float)NROWS;

    if (k == 0) {
        float m1 = g_S1[j] * invN;
        float v1 = g_S2[j * HID + j] * invN - m1 * m1;
        m1s[j] = m1;
        a1s[j] = g1[j] * rsqrtf(v1 + EPSV);
    }
    __syncthreads();
    // thread (k,j): C[k][j], qv[k][j]
    Cm[k][j] = g_S2[k * HID + j] * invN - m1s[k] * m1s[j];
    qv[k][j] = a1s[k] * Wl2[k * HID + j];
    __syncthreads();
    // part[k][j] = qv[k][j] * sum_l qv[l][j] * C[k][l]
    float acc = 0.f;
    #pragma unroll 8
    for (int l = 0; l < HID; l++) acc = fmaf(qv[l][j], Cm[k][l], acc);
    part[k][j] = qv[k][j] * acc;
    __syncthreads();

    if (k == 0) {
        float vy = 0.f;
        #pragma unroll
        for (int kk = 0; kk < HID; kk++) vy += part[kk][j];
        float my = bl2[j];
        #pragma unroll
        for (int kk = 0; kk < HID; kk++) my = fmaf(be1[kk], Wl2[kk * HID + j], my);
        float a2 = g2[j] * rsqrtf(vy + EPSV);
        a2s[j] = a2;
        float cpart = fmaf(a2, bl2[j] - my, be2[j]);
        __syncwarp();
        float wt = 0.f;
        #pragma unroll
        for (int jj = 0; jj < HID; jj++) wt = fmaf(Wl2[j * HID + jj], a2s[jj], wt);
        g_u[j] = a1s[j] * wt;
        cpart = fmaf(be1[j] - a1s[j] * m1s[j], wt, cpart);
        #pragma unroll
        for (int off = 16; off > 0; off >>= 1) cpart += __shfl_down_sync(0xffffffffu, cpart, off);
        if (j == 0) g_c0 = cpart;
    }
}

// ---- K4: out = rest + x1 . u + c0 ----
__global__ __launch_bounds__(256) void out_kernel(float* __restrict__ out) {
    __shared__ float us[HID];
    __shared__ float c0s;
    if (threadIdx.x < HID) us[threadIdx.x] = g_u[threadIdx.x];
    if (threadIdx.x == HID) c0s = g_c0;
    __syncthreads();
    int n = blockIdx.x * blockDim.x + threadIdx.x;
    float acc = g_rest[n] + c0s;
    #pragma unroll
    for (int j = 0; j < HID; j++)
        acc = fmaf(g_x1[(size_t)j * NROWS + n], us[j], acc);
    out[n] = acc;
}

extern "C" void kernel_launch(void* const* d_in, const int* in_sizes, int n_in,
                              void* d_out, int out_size) {
    const float* Xi_dense  = (const float*)d_in[0];
    const int*   Xi_sparse = (const int*)d_in[1];
    const float* Xv   = (const float*)d_in[2];
    const float* bias = (const float*)d_in[3];
    const float* W1d  = (const float*)d_in[4];
    const float* b1d  = (const float*)d_in[5];
    const float* T1   = (const float*)d_in[6];
    const float* W2d  = (const float*)d_in[7];
    const float* b2d  = (const float*)d_in[8];
    const float* T2   = (const float*)d_in[9];
    const float* Wl1  = (const float*)d_in[10];
    const float* bl1  = (const float*)d_in[11];
    const float* g1   = (const float*)d_in[12];
    const float* be1  = (const float*)d_in[13];
    const float* Wl2  = (const float*)d_in[14];
    const float* bl2  = (const float*)d_in[15];
    const float* g2   = (const float*)d_in[16];
    const float* be2  = (const float*)d_in[17];
    float* out = (float*)d_out;

    size_t smem = (size_t)(SWROWS * SWSTRIDE + 2 * NDENSE * HID + 2 * NDENSE * EMBD
                           + 2 * NDENSE + HID) * sizeof(float);
    cudaFuncSetAttribute(main_kernel, cudaFuncAttributeMaxDynamicSharedMemorySize, (int)smem);

    pre_kernel<<<1, 1024>>>(W1d, b1d, W2d, b2d, Wl1);
    main_kernel<<<NROWS / 64, 256, smem>>>(Xi_dense, Xi_sparse, Xv, bias,
                                           T1, T2, W2d, b2d, Wl1, bl1);
    stats_kernel<<<256, 1024>>>();
    fin_kernel<<<1, 1024>>>(g1, be1, Wl2, bl2, g2, be2);
    out_kernel<<<NROWS / 256, 256>>>(out);
}

// round 5
// speedup vs baseline: 1.5278x; 1.5278x over previous
#include <cuda_runtime.h>
#include <cstdint>
#include <cstddef>

#define NROWS 131072
#define NDENSE 13
#define NSPARSE 26
#define NFIELD 39
#define EMBD 16
#define HID 32
#define VOCABSZ 100000
#define EPSV 1e-5f
#define SWROWS (NSPARSE * EMBD)   // 416 sparse rows of Wl1
#define SWSTRIDE 36               // padded (floats); quad lanes 4 banks apart
#define A2STRIDE 34               // padded (floats); 8B-aligned rows, conflict-free

// ---- scratch (static device globals; no allocation) ----
__device__ float g_x1[(size_t)HID * NROWS];   // column-major [HID][NROWS]
__device__ float g_rest[NROWS];
__device__ float g_S1[HID];
__device__ float g_S2[HID * HID];
__device__ float g_u[HID];
__device__ float g_c0;
__device__ int   g_cnt;

// ---- packed f32x2 helpers (Blackwell) ----
typedef unsigned long long ull;
__device__ __forceinline__ ull pk2(float a, float b) {
    ull r;
    asm("mov.b64 %0, {%1, %2};" : "=l"(r)
        : "r"(__float_as_uint(a)), "r"(__float_as_uint(b)));
    return r;
}
__device__ __forceinline__ void upk2(ull v, float& a, float& b) {
    unsigned int x, y;
    asm("mov.b64 {%0, %1}, %2;" : "=r"(x), "=r"(y) : "l"(v));
    a = __uint_as_float(x); b = __uint_as_float(y);
}
__device__ __forceinline__ ull fma2(ull a, ull b, ull c) {
    ull d;
    asm("fma.rn.f32x2 %0, %1, %2, %3;" : "=l"(d) : "l"(a), "l"(b), "l"(c));
    return d;
}
__device__ __forceinline__ ull add2(ull a, ull b) {
    ull d;
    asm("add.rn.f32x2 %0, %1, %2;" : "=l"(d) : "l"(a), "l"(b));
    return d;
}

// ---- K1: fused embed + FM + deep@Wl1 — quad-cooperative, 128 rows/block ----
__global__ __launch_bounds__(256, 2) void main_kernel(
    const float* __restrict__ Xi_dense, const int* __restrict__ Xi_sparse,
    const float* __restrict__ Xv, const float* __restrict__ bias,
    const float* __restrict__ T1, const float* __restrict__ T2,
    const float* __restrict__ W1d, const float* __restrict__ b1d,
    const float* __restrict__ W2d, const float* __restrict__ b2d,
    const float* __restrict__ Wl1, const float* __restrict__ bl1)
{
    extern __shared__ float sm[];
    float* sWl1 = sm;                              // 416*36 = 14976
    float* sA2  = sWl1 + SWROWS * SWSTRIDE;        // 13*34 = 442
    float* sB2  = sA2 + NDENSE * A2STRIDE;         // 442
    float* sW2  = sB2 + NDENSE * A2STRIDE;         // 208
    float* sb2  = sW2 + NDENSE * EMBD;             // 208
    float* sw1  = sb2 + NDENSE * EMBD;             // 13
    float* sb1  = sw1 + NDENSE;                    // 13
    float* sbl  = sb1 + NDENSE;                    // 32

    // sparse rows of Wl1, permuted so lane ql's rows sit 36 floats apart
    for (int i = threadIdx.x; i < SWROWS * HID; i += 256) {
        int r = i >> 5, c = i & 31;
        int f = r >> 4, e = r & 15;
        int pr = (f << 4) + ((e & 3) << 2) + (e >> 2);
        sWl1[pr * SWSTRIDE + c] = Wl1[(NDENSE * EMBD + r) * HID + c];
    }
    // fold dense projections: A2 = W2d row . Wl1 cols, B2 = b2d row . Wl1 cols
    for (int i = threadIdx.x; i < NDENSE * HID; i += 256) {
        int f = i >> 5, j = i & 31;
        float a = 0.f, b = 0.f;
        #pragma unroll
        for (int e = 0; e < EMBD; e++) {
            float w = Wl1[(f * EMBD + e) * HID + j];
            a = fmaf(W2d[f * EMBD + e], w, a);
            b = fmaf(b2d[f * EMBD + e], w, b);
        }
        sA2[f * A2STRIDE + j] = a;
        sB2[f * A2STRIDE + j] = b;
    }
    if (threadIdx.x < NDENSE * EMBD) {
        sW2[threadIdx.x] = W2d[threadIdx.x];
        sb2[threadIdx.x] = b2d[threadIdx.x];
    }
    if (threadIdx.x < NDENSE) {
        float a = 0.f, b = 0.f;
        #pragma unroll
        for (int e = 0; e < EMBD; e++) {
            a += W1d[threadIdx.x * EMBD + e];
            b += b1d[threadIdx.x * EMBD + e];
        }
        sw1[threadIdx.x] = a; sb1[threadIdx.x] = b;
    }
    if (threadIdx.x >= 224) sbl[threadIdx.x - 224] = bl1[threadIdx.x - 224];
    if (blockIdx.x == 0) {
        if (threadIdx.x < HID) g_S1[threadIdx.x] = 0.f;
        for (int i = threadIdx.x; i < HID * HID; i += 256) g_S2[i] = 0.f;
        if (threadIdx.x == 0) g_cnt = 0;
    }
    __syncthreads();

    const int warp = threadIdx.x >> 5;
    const int lane = threadIdx.x & 31;
    const int quad = lane >> 2;
    const int ql   = lane & 3;

    #pragma unroll 1
    for (int g = 0; g < 2; g++) {
        const int row = blockIdx.x * 128 + g * 64 + warp * 8 + quad;

        ull x1p[16];
        #pragma unroll
        for (int i = 0; i < 16; i++) x1p[i] = 0ull;
        ull s01 = 0ull, s23 = 0ull, sqp = 0ull;
        float rest = (ql == 0) ? __ldg(bias + row) : 0.f;

        const float* xvp = Xv + (size_t)row * NFIELD;
        const float* xdp = Xi_dense + (size_t)row * NDENSE;
        const int*   xsp = Xi_sparse + (size_t)row * NSPARSE;

        // ---- dense fields: FM terms (e-split), stash for f-split projection ----
        float vst[4], xst[4];
        #pragma unroll
        for (int f = 0; f < NDENSE; f++) {
            float v  = __ldg(xvp + f);
            float xi = __ldg(xdp + f);
            if ((f & 3) == ql) { vst[f >> 2] = v; xst[f >> 2] = xi; }
            if (ql == 0) rest = fmaf(v, fmaf(xi, sw1[f], sb1[f]), rest);
            int eb = f * EMBD + ql * 4;
            float t0 = fmaf(xi, sW2[eb + 0], sb2[eb + 0]) * v;
            float t1 = fmaf(xi, sW2[eb + 1], sb2[eb + 1]) * v;
            float t2 = fmaf(xi, sW2[eb + 2], sb2[eb + 2]) * v;
            float t3 = fmaf(xi, sW2[eb + 3], sb2[eb + 3]) * v;
            ull p01 = pk2(t0, t1), p23 = pk2(t2, t3);
            s01 = add2(s01, p01); s23 = add2(s23, p23);
            sqp = fma2(p01, p01, sqp); sqp = fma2(p23, p23, sqp);
        }
        // dense x1 projection, fields split across quad lanes (f = 4m + ql)
        #pragma unroll
        for (int m = 0; m < 4; m++) {
            int f = 4 * m + ql;
            if (f < NDENSE) {
                float vv = vst[m];
                float xiv = xst[m] * vv;
                ull xp = pk2(xiv, xiv), vp = pk2(vv, vv);
                const ull* A = (const ull*)(sA2 + f * A2STRIDE);
                const ull* B = (const ull*)(sB2 + f * A2STRIDE);
                #pragma unroll
                for (int jp = 0; jp < 16; jp++) {
                    x1p[jp] = fma2(xp, A[jp], x1p[jp]);
                    x1p[jp] = fma2(vp, B[jp], x1p[jp]);
                }
            }
        }

        // ---- sparse fields: quad-cooperative 16B gathers, 1-ahead prefetch ----
        int    idx0 = __ldg(xsp);
        float  vnx  = __ldg(xvp + NDENSE);
        size_t b0   = ((size_t)idx0) * EMBD + (size_t)(ql * 4);
        float4 a = __ldcg((const float4*)(T1 + b0));
        float4 b = __ldcg((const float4*)(T2 + b0));
        #pragma unroll 1
        for (int f = 0; f < NSPARSE; f++) {
            float4 ca = a, cb = b;
            float  cv = vnx;
            if (f + 1 < NSPARSE) {
                int idxn = __ldg(xsp + f + 1);
                vnx = __ldg(xvp + NDENSE + f + 1);
                size_t bn = ((size_t)(f + 1) * VOCABSZ + (size_t)idxn) * EMBD + (size_t)(ql * 4);
                a = __ldcg((const float4*)(T1 + bn));
                b = __ldcg((const float4*)(T2 + bn));
            }
            rest = fmaf(cv, (ca.x + ca.y) + (ca.z + ca.w), rest);
            float tv0 = cb.x * cv, tv1 = cb.y * cv, tv2 = cb.z * cv, tv3 = cb.w * cv;
            ull p01 = pk2(tv0, tv1), p23 = pk2(tv2, tv3);
            s01 = add2(s01, p01); s23 = add2(s23, p23);
            sqp = fma2(p01, p01, sqp); sqp = fma2(p23, p23, sqp);
            const float* wb = sWl1 + f * (16 * SWSTRIDE) + ql * SWSTRIDE;
            {
                ull te = pk2(tv0, tv0);
                const ulonglong2* w = (const ulonglong2*)(wb);
                #pragma unroll
                for (int q = 0; q < 8; q++) {
                    ulonglong2 ww = w[q];
                    x1p[2 * q]     = fma2(te, ww.x, x1p[2 * q]);
                    x1p[2 * q + 1] = fma2(te, ww.y, x1p[2 * q + 1]);
                }
            }
            {
                ull te = pk2(tv1, tv1);
                const ulonglong2* w = (const ulonglong2*)(wb + 4 * SWSTRIDE);
                #pragma unroll
                for (int q = 0; q < 8; q++) {
                    ulonglong2 ww = w[q];
                    x1p[2 * q]     = fma2(te, ww.x, x1p[2 * q]);
                    x1p[2 * q + 1] = fma2(te, ww.y, x1p[2 * q + 1]);
                }
            }
            {
                ull te = pk2(tv2, tv2);
                const ulonglong2* w = (const ulonglong2*)(wb + 8 * SWSTRIDE);
                #pragma unroll
                for (int q = 0; q < 8; q++) {
                    ulonglong2 ww = w[q];
                    x1p[2 * q]     = fma2(te, ww.x, x1p[2 * q]);
                    x1p[2 * q + 1] = fma2(te, ww.y, x1p[2 * q + 1]);
                }
            }
            {
                ull te = pk2(tv3, tv3);
                const ulonglong2* w = (const ulonglong2*)(wb + 12 * SWSTRIDE);
                #pragma unroll
                for (int q = 0; q < 8; q++) {
                    ulonglong2 ww = w[q];
                    x1p[2 * q]     = fma2(te, ww.x, x1p[2 * q]);
                    x1p[2 * q + 1] = fma2(te, ww.y, x1p[2 * q + 1]);
                }
            }
        }

        // ---- epilogue: FM scalar, quad butterfly reduce ----
        {
            ull f2 = fma2(s01, s01, 0ull);
            f2 = fma2(s23, s23, f2);
            float flo, fhi; upk2(f2, flo, fhi);
            float qlo, qhi; upk2(sqp, qlo, qhi);
            rest += 0.5f * ((flo + fhi) - (qlo + qhi));
        }
        rest += __shfl_xor_sync(0xffffffffu, rest, 1);
        rest += __shfl_xor_sync(0xffffffffu, rest, 2);
        #pragma unroll
        for (int jp = 0; jp < 16; jp++) {
            ull v = x1p[jp];
            v = add2(v, __shfl_xor_sync(0xffffffffu, v, 1));
            v = add2(v, __shfl_xor_sync(0xffffffffu, v, 2));
            x1p[jp] = v;
        }
        if (ql == 0) {
            g_rest[row] = rest;
            #pragma unroll
            for (int jp = 0; jp < 16; jp++) {
                float lo, hi; upk2(x1p[jp], lo, hi);
                g_x1[(size_t)(2 * jp) * NROWS + row]     = lo + sbl[2 * jp];
                g_x1[(size_t)(2 * jp + 1) * NROWS + row] = hi + sbl[2 * jp + 1];
            }
        }
    }
}

// ---- K2: S1 / S2 reduction; last block folds BN -> u, c0 ----
__global__ __launch_bounds__(1024) void stats_kernel(
        const float* __restrict__ g1, const float* __restrict__ be1,
        const float* __restrict__ Wl2, const float* __restrict__ bl2,
        const float* __restrict__ g2, const float* __restrict__ be2) {
    __shared__ float tile[HID][257];
    const int k = threadIdx.x >> 5;
    const int l = threadIdx.x & 31;
    float acc = 0.f, acc1 = 0.f;
    for (int chunk = blockIdx.x; chunk < NROWS / 256; chunk += gridDim.x) {
        int r0 = chunk * 256;
        #pragma unroll
        for (int i = 0; i < 8; i++) {
            int idx = threadIdx.x + i * 1024;
            int col = idx >> 8;
            int r = idx & 255;
            tile[col][r] = g_x1[(size_t)col * NROWS + r0 + r];
        }
        __syncthreads();
        #pragma unroll 8
        for (int r = 0; r < 256; r++) {
            float xk = tile[k][r];
            float xl = tile[l][r];
            acc = fmaf(xk, xl, acc);
            acc1 += xk;
        }
        __syncthreads();
    }
    atomicAdd(&g_S2[k * HID + l], acc);
    if (l == 0) atomicAdd(&g_S1[k], acc1);
    __syncthreads();

    // last-finishing block computes the closed-form BN fold
    __shared__ int isLast;
    if (threadIdx.x == 0) {
        __threadfence();
        int old = atomicAdd(&g_cnt, 1);
        isLast = (old == (int)gridDim.x - 1) ? 1 : 0;
    }
    __syncthreads();
    if (!isLast) return;

    __shared__ float m1s[HID], a1s[HID], a2s[HID];
    __shared__ float qv[HID][HID + 1];
    __shared__ float Cm[HID][HID + 1];
    __shared__ float part[HID][HID + 1];
    const int j = l;
    const float invN = 1.f / (float)NROWS;

    if (k == 0) {
        float m1 = __ldcg(&g_S1[j]) * invN;
        float v1 = __ldcg(&g_S2[j * HID + j]) * invN - m1 * m1;
        m1s[j] = m1;
        a1s[j] = g1[j] * rsqrtf(v1 + EPSV);
    }
    __syncthreads();
    Cm[k][j] = __ldcg(&g_S2[k * HID + j]) * invN - m1s[k] * m1s[j];
    qv[k][j] = a1s[k] * Wl2[k * HID + j];
    __syncthreads();
    float accv = 0.f;
    #pragma unroll 8
    for (int ll = 0; ll < HID; ll++) accv = fmaf(qv[ll][j], Cm[k][ll], accv);
    part[k][j] = qv[k][j] * accv;
    __syncthreads();

    if (k == 0) {
        float vy = 0.f;
        #pragma unroll
        for (int kk = 0; kk < HID; kk++) vy += part[kk][j];
        float my = bl2[j];
        #pragma unroll
        for (int kk = 0; kk < HID; kk++) my = fmaf(be1[kk], Wl2[kk * HID + j], my);
        float a2 = g2[j] * rsqrtf(vy + EPSV);
        a2s[j] = a2;
        float cpart = fmaf(a2, bl2[j] - my, be2[j]);
        __syncwarp();
        float wt = 0.f;
        #pragma unroll
        for (int jj = 0; jj < HID; jj++) wt = fmaf(Wl2[j * HID + jj], a2s[jj], wt);
        g_u[j] = a1s[j] * wt;
        cpart = fmaf(be1[j] - a1s[j] * m1s[j], wt, cpart);
        #pragma unroll
        for (int off = 16; off > 0; off >>= 1) cpart += __shfl_down_sync(0xffffffffu, cpart, off);
        if (j == 0) g_c0 = cpart;
    }
}

// ---- K3: out = rest + x1 . u + c0 ----
__global__ __launch_bounds__(256) void out_kernel(float* __restrict__ out) {
    __shared__ float us[HID];
    __shared__ float c0s;
    if (threadIdx.x < HID) us[threadIdx.x] = g_u[threadIdx.x];
    if (threadIdx.x == HID) c0s = g_c0;
    __syncthreads();
    int n = blockIdx.x * blockDim.x + threadIdx.x;
    float acc = g_rest[n] + c0s;
    #pragma unroll
    for (int j = 0; j < HID; j++)
        acc = fmaf(g_x1[(size_t)j * NROWS + n], us[j], acc);
    out[n] = acc;
}

extern "C" void kernel_launch(void* const* d_in, const int* in_sizes, int n_in,
                              void* d_out, int out_size) {
    const float* Xi_dense  = (const float*)d_in[0];
    const int*   Xi_sparse = (const int*)d_in[1];
    const float* Xv   = (const float*)d_in[2];
    const float* bias = (const float*)d_in[3];
    const float* W1d  = (const float*)d_in[4];
    const float* b1d  = (const float*)d_in[5];
    const float* T1   = (const float*)d_in[6];
    const float* W2d  = (const float*)d_in[7];
    const float* b2d  = (const float*)d_in[8];
    const float* T2   = (const float*)d_in[9];
    const float* Wl1  = (const float*)d_in[10];
    const float* bl1  = (const float*)d_in[11];
    const float* g1   = (const float*)d_in[12];
    const float* be1  = (const float*)d_in[13];
    const float* Wl2  = (const float*)d_in[14];
    const float* bl2  = (const float*)d_in[15];
    const float* g2   = (const float*)d_in[16];
    const float* be2  = (const float*)d_in[17];
    float* out = (float*)d_out;

    size_t smem = (size_t)(SWROWS * SWSTRIDE + 2 * NDENSE * A2STRIDE
                           + 2 * NDENSE * EMBD + 2 * NDENSE + HID + 8) * sizeof(float);
    cudaFuncSetAttribute(main_kernel, cudaFuncAttributeMaxDynamicSharedMemorySize, (int)smem);

    main_kernel<<<NROWS / 128, 256, smem>>>(Xi_dense, Xi_sparse, Xv, bias,
                                            T1, T2, W1d, b1d, W2d, b2d, Wl1, bl1);
    stats_kernel<<<256, 1024>>>(g1, be1, Wl2, bl2, g2, be2);
    out_kernel<<<NROWS / 256, 256>>>(out);
}

// round 6
// speedup vs baseline: 1.5375x; 1.0063x over previous
#include <cuda_runtime.h>
#include <cstdint>
#include <cstddef>

#define NROWS 131072
#define NDENSE 13
#define NSPARSE 26
#define NFIELD 39
#define EMBD 16
#define HID 32
#define VOCABSZ 100000
#define EPSV 1e-5f
#define SWROWS (NSPARSE * EMBD)   // 416 sparse rows of Wl1, row-major stride 32

// ---- scratch (static device globals; no allocation) ----
__device__ float g_x1[(size_t)HID * NROWS];   // column-major [HID][NROWS]
__device__ float g_rest[NROWS];
__device__ float g_S1[HID];
__device__ float g_S2[HID * HID];
__device__ float g_u[HID];
__device__ float g_c0;
__device__ int   g_cnt;

// ---- packed f32x2 helpers (Blackwell) ----
typedef unsigned long long ull;
__device__ __forceinline__ ull pk2(float a, float b) {
    ull r;
    asm("mov.b64 %0, {%1, %2};" : "=l"(r)
        : "r"(__float_as_uint(a)), "r"(__float_as_uint(b)));
    return r;
}
__device__ __forceinline__ void upk2(ull v, float& a, float& b) {
    unsigned int x, y;
    asm("mov.b64 {%0, %1}, %2;" : "=r"(x), "=r"(y) : "l"(v));
    a = __uint_as_float(x); b = __uint_as_float(y);
}
__device__ __forceinline__ ull fma2(ull a, ull b, ull c) {
    ull d;
    asm("fma.rn.f32x2 %0, %1, %2, %3;" : "=l"(d) : "l"(a), "l"(b), "l"(c));
    return d;
}
__device__ __forceinline__ ull add2(ull a, ull b) {
    ull d;
    asm("add.rn.f32x2 %0, %1, %2;" : "=l"(d) : "l"(a), "l"(b));
    return d;
}

// ---- K1: fused embed + FM + deep@Wl1 ----
// Warp = 8 rows. Gathers: quad-cooperative (lane ql loads 16B chunk e∈[4ql,4ql+4)).
// Projection: lane (q,ql) owns cols [8ql,8ql+8) of row q; t values redistributed
// by 32-bit shuffles; Wl1 smem reads are warp-broadcast (1 wavefront / LDS.128).
__global__ __launch_bounds__(256, 3) void main_kernel(
    const float* __restrict__ Xi_dense, const int* __restrict__ Xi_sparse,
    const float* __restrict__ Xv, const float* __restrict__ bias,
    const float* __restrict__ T1, const float* __restrict__ T2,
    const float* __restrict__ W1d, const float* __restrict__ b1d,
    const float* __restrict__ W2d, const float* __restrict__ b2d,
    const float* __restrict__ Wl1, const float* __restrict__ bl1)
{
    extern __shared__ float sm[];
    float* sWl1 = sm;                          // 416*32 = 13312
    float* sA2  = sWl1 + SWROWS * HID;         // 13*32 = 416
    float* sB2  = sA2 + NDENSE * HID;          // 416
    float* sW2  = sB2 + NDENSE * HID;          // 208
    float* sb2  = sW2 + NDENSE * EMBD;         // 208
    float* sbl  = sb2 + NDENSE * EMBD;         // 32 (8B-aligned offset)
    float* sw1  = sbl + HID;                   // 13
    float* sb1  = sw1 + NDENSE;                // 13

    // flat copy of sparse rows of Wl1 (global rows 208..623)
    for (int i = threadIdx.x; i < SWROWS * HID; i += 256)
        sWl1[i] = Wl1[NDENSE * EMBD * HID + i];
    // fold dense projections
    for (int i = threadIdx.x; i < NDENSE * HID; i += 256) {
        int f = i >> 5, j = i & 31;
        float a = 0.f, b = 0.f;
        #pragma unroll
        for (int e = 0; e < EMBD; e++) {
            float w = Wl1[(f * EMBD + e) * HID + j];
            a = fmaf(W2d[f * EMBD + e], w, a);
            b = fmaf(b2d[f * EMBD + e], w, b);
        }
        sA2[i] = a; sB2[i] = b;
    }
    if (threadIdx.x < NDENSE * EMBD) {
        sW2[threadIdx.x] = W2d[threadIdx.x];
        sb2[threadIdx.x] = b2d[threadIdx.x];
    }
    if (threadIdx.x < NDENSE) {
        float a = 0.f, b = 0.f;
        #pragma unroll
        for (int e = 0; e < EMBD; e++) {
            a += W1d[threadIdx.x * EMBD + e];
            b += b1d[threadIdx.x * EMBD + e];
        }
        sw1[threadIdx.x] = a; sb1[threadIdx.x] = b;
    }
    if (threadIdx.x >= 224) sbl[threadIdx.x - 224] = bl1[threadIdx.x - 224];
    if (blockIdx.x == 0) {
        if (threadIdx.x < HID) g_S1[threadIdx.x] = 0.f;
        for (int i = threadIdx.x; i < HID * HID; i += 256) g_S2[i] = 0.f;
        if (threadIdx.x == 0) g_cnt = 0;
    }
    __syncthreads();

    const int warp = threadIdx.x >> 5;
    const int lane = threadIdx.x & 31;
    const int q    = lane >> 2;          // row within octet
    const int ql   = lane & 3;           // e-group (gather) / col-group (fma)
    const int qbase = lane & ~3;

    #pragma unroll 1
    for (int g = 0; g < 2; g++) {
        const int row = blockIdx.x * 128 + g * 64 + warp * 8 + q;

        ull x1p[4];                      // cols [8ql, 8ql+8) of row, packed
        x1p[0] = x1p[1] = x1p[2] = x1p[3] = 0ull;
        ull s01 = 0ull, s23 = 0ull, sqp = 0ull;
        float rest = (ql == 0) ? __ldg(bias + row) : 0.f;

        const float* xvp = Xv + (size_t)row * NFIELD;
        const float* xdp = Xi_dense + (size_t)row * NDENSE;
        const int*   xsp = Xi_sparse + (size_t)row * NSPARSE;

        // ---- dense fields ----
        #pragma unroll
        for (int f = 0; f < NDENSE; f++) {
            float v  = __ldg(xvp + f);
            float xi = __ldg(xdp + f);
            if (ql == 0) rest = fmaf(v, fmaf(xi, sw1[f], sb1[f]), rest);
            // FM (e-split over quad)
            int eb = f * EMBD + ql * 4;
            float t0 = fmaf(xi, sW2[eb + 0], sb2[eb + 0]) * v;
            float t1 = fmaf(xi, sW2[eb + 1], sb2[eb + 1]) * v;
            float t2 = fmaf(xi, sW2[eb + 2], sb2[eb + 2]) * v;
            float t3 = fmaf(xi, sW2[eb + 3], sb2[eb + 3]) * v;
            ull p01 = pk2(t0, t1), p23 = pk2(t2, t3);
            s01 = add2(s01, p01); s23 = add2(s23, p23);
            sqp = fma2(p01, p01, sqp); sqp = fma2(p23, p23, sqp);
            // projection: own 8 cols via folded A2/B2 (broadcast reads)
            float xiv = xi * v;
            ull xp = pk2(xiv, xiv), vp = pk2(v, v);
            const ulonglong2* A = (const ulonglong2*)(sA2 + f * HID + ql * 8);
            const ulonglong2* B = (const ulonglong2*)(sB2 + f * HID + ql * 8);
            ulonglong2 a0 = A[0], a1 = A[1];
            ulonglong2 b0 = B[0], b1 = B[1];
            x1p[0] = fma2(xp, a0.x, x1p[0]); x1p[1] = fma2(xp, a0.y, x1p[1]);
            x1p[2] = fma2(xp, a1.x, x1p[2]); x1p[3] = fma2(xp, a1.y, x1p[3]);
            x1p[0] = fma2(vp, b0.x, x1p[0]); x1p[1] = fma2(vp, b0.y, x1p[1]);
            x1p[2] = fma2(vp, b1.x, x1p[2]); x1p[3] = fma2(vp, b1.y, x1p[3]);
        }

        // ---- sparse fields: quad gathers + broadcast projection ----
        int    idx0 = __ldg(xsp);
        float  vnx  = __ldg(xvp + NDENSE);
        size_t bas0 = ((size_t)idx0) * EMBD + (size_t)(ql * 4);
        float4 pa = __ldcg((const float4*)(T1 + bas0));
        float4 pb = __ldcg((const float4*)(T2 + bas0));

        #pragma unroll 1
        for (int f = 0; f < NSPARSE; f++) {
            float4 ca = pa, cb = pb;
            float  cv = vnx;
            if (f + 1 < NSPARSE) {
                int idxn = __ldg(xsp + f + 1);
                vnx = __ldg(xvp + NDENSE + f + 1);
                size_t bn = ((size_t)(f + 1) * VOCABSZ + (size_t)idxn) * EMBD
                            + (size_t)(ql * 4);
                pa = __ldcg((const float4*)(T1 + bn));
                pb = __ldcg((const float4*)(T2 + bn));
            }
            rest = fmaf(cv, (ca.x + ca.y) + (ca.z + ca.w), rest);
            float tv[4];
            tv[0] = cb.x * cv; tv[1] = cb.y * cv; tv[2] = cb.z * cv; tv[3] = cb.w * cv;
            ull p01 = pk2(tv[0], tv[1]), p23 = pk2(tv[2], tv[3]);
            s01 = add2(s01, p01); s23 = add2(s23, p23);
            sqp = fma2(p01, p01, sqp); sqp = fma2(p23, p23, sqp);

            const float* wb = sWl1 + f * (EMBD * HID) + ql * 8;
            #pragma unroll
            for (int e = 0; e < EMBD; e++) {
                float t = __shfl_sync(0xffffffffu, tv[e & 3], qbase | (e >> 2));
                ull te = pk2(t, t);
                const ulonglong2* w = (const ulonglong2*)(wb + e * HID);
                ulonglong2 w0 = w[0], w1 = w[1];
                x1p[0] = fma2(te, w0.x, x1p[0]);
                x1p[1] = fma2(te, w0.y, x1p[1]);
                x1p[2] = fma2(te, w1.x, x1p[2]);
                x1p[3] = fma2(te, w1.y, x1p[3]);
            }
        }

        // ---- FM scalar epilogue + quad reduce of rest ----
        {
            ull f2 = fma2(s01, s01, 0ull);
            f2 = fma2(s23, s23, f2);
            float flo, fhi; upk2(f2, flo, fhi);
            float qlo, qhi; upk2(sqp, qlo, qhi);
            rest += 0.5f * ((flo + fhi) - (qlo + qhi));
        }
        rest += __shfl_xor_sync(0xffffffffu, rest, 1);
        rest += __shfl_xor_sync(0xffffffffu, rest, 2);
        if (ql == 0) g_rest[row] = rest;

        // ---- store x1 (each lane owns full sums for its 8 cols) ----
        #pragma unroll
        for (int i = 0; i < 4; i++) {
            ull blp = *(const ull*)(sbl + ql * 8 + 2 * i);
            ull v = add2(x1p[i], blp);
            float lo, hi; upk2(v, lo, hi);
            g_x1[(size_t)(ql * 8 + 2 * i) * NROWS + row]     = lo;
            g_x1[(size_t)(ql * 8 + 2 * i + 1) * NROWS + row] = hi;
        }
    }
}

// ---- K2: S1 / S2 reduction; last block folds BN -> u, c0 ----
__global__ __launch_bounds__(1024) void stats_kernel(
        const float* __restrict__ g1, const float* __restrict__ be1,
        const float* __restrict__ Wl2, const float* __restrict__ bl2,
        const float* __restrict__ g2, const float* __restrict__ be2) {
    __shared__ float tile[HID][257];
    const int k = threadIdx.x >> 5;
    const int l = threadIdx.x & 31;
    float acc = 0.f, acc1 = 0.f;
    for (int chunk = blockIdx.x; chunk < NROWS / 256; chunk += gridDim.x) {
        int r0 = chunk * 256;
        #pragma unroll
        for (int i = 0; i < 8; i++) {
            int idx = threadIdx.x + i * 1024;
            int col = idx >> 8;
            int r = idx & 255;
            tile[col][r] = g_x1[(size_t)col * NROWS + r0 + r];
        }
        __syncthreads();
        #pragma unroll 8
        for (int r = 0; r < 256; r++) {
            float xk = tile[k][r];
            float xl = tile[l][r];
            acc = fmaf(xk, xl, acc);
            acc1 += xk;
        }
        __syncthreads();
    }
    atomicAdd(&g_S2[k * HID + l], acc);
    if (l == 0) atomicAdd(&g_S1[k], acc1);
    __syncthreads();

    __shared__ int isLast;
    if (threadIdx.x == 0) {
        __threadfence();
        int old = atomicAdd(&g_cnt, 1);
        isLast = (old == (int)gridDim.x - 1) ? 1 : 0;
    }
    __syncthreads();
    if (!isLast) return;

    __shared__ float m1s[HID], a1s[HID], a2s[HID];
    __shared__ float qv[HID][HID + 1];
    __shared__ float Cm[HID][HID + 1];
    __shared__ float part[HID][HID + 1];
    const int j = l;
    const float invN = 1.f / (float)NROWS;

    if (k == 0) {
        float m1 = __ldcg(&g_S1[j]) * invN;
        float v1 = __ldcg(&g_S2[j * HID + j]) * invN - m1 * m1;
        m1s[j] = m1;
        a1s[j] = g1[j] * rsqrtf(v1 + EPSV);
    }
    __syncthreads();
    Cm[k][j] = __ldcg(&g_S2[k * HID + j]) * invN - m1s[k] * m1s[j];
    qv[k][j] = a1s[k] * Wl2[k * HID + j];
    __syncthreads();
    float accv = 0.f;
    #pragma unroll 8
    for (int ll = 0; ll < HID; ll++) accv = fmaf(qv[ll][j], Cm[k][ll], accv);
    part[k][j] = qv[k][j] * accv;
    __syncthreads();

    if (k == 0) {
        float vy = 0.f;
        #pragma unroll
        for (int kk = 0; kk < HID; kk++) vy += part[kk][j];
        float my = bl2[j];
        #pragma unroll
        for (int kk = 0; kk < HID; kk++) my = fmaf(be1[kk], Wl2[kk * HID + j], my);
        float a2 = g2[j] * rsqrtf(vy + EPSV);
        a2s[j] = a2;
        float cpart = fmaf(a2, bl2[j] - my, be2[j]);
        __syncwarp();
        float wt = 0.f;
        #pragma unroll
        for (int jj = 0; jj < HID; jj++) wt = fmaf(Wl2[j * HID + jj], a2s[jj], wt);
        g_u[j] = a1s[j] * wt;
        cpart = fmaf(be1[j] - a1s[j] * m1s[j], wt, cpart);
        #pragma unroll
        for (int off = 16; off > 0; off >>= 1) cpart += __shfl_down_sync(0xffffffffu, cpart, off);
        if (j == 0) g_c0 = cpart;
    }
}

// ---- K3: out = rest + x1 . u + c0 ----
__global__ __launch_bounds__(256) void out_kernel(float* __restrict__ out) {
    __shared__ float us[HID];
    __shared__ float c0s;
    if (threadIdx.x < HID) us[threadIdx.x] = g_u[threadIdx.x];
    if (threadIdx.x == HID) c0s = g_c0;
    __syncthreads();
    int n = blockIdx.x * blockDim.x + threadIdx.x;
    float acc = g_rest[n] + c0s;
    #pragma unroll
    for (int j = 0; j < HID; j++)
        acc = fmaf(g_x1[(size_t)j * NROWS + n], us[j], acc);
    out[n] = acc;
}

extern "C" void kernel_launch(void* const* d_in, const int* in_sizes, int n_in,
                              void* d_out, int out_size) {
    const float* Xi_dense  = (const float*)d_in[0];
    const int*   Xi_sparse = (const int*)d_in[1];
    const float* Xv   = (const float*)d_in[2];
    const float* bias = (const float*)d_in[3];
    const float* W1d  = (const float*)d_in[4];
    const float* b1d  = (const float*)d_in[5];
    const float* T1   = (const float*)d_in[6];
    const float* W2d  = (const float*)d_in[7];
    const float* b2d  = (const float*)d_in[8];
    const float* T2   = (const float*)d_in[9];
    const float* Wl1  = (const float*)d_in[10];
    const float* bl1  = (const float*)d_in[11];
    const float* g1   = (const float*)d_in[12];
    const float* be1  = (const float*)d_in[13];
    const float* Wl2  = (const float*)d_in[14];
    const float* bl2  = (const float*)d_in[15];
    const float* g2   = (const float*)d_in[16];
    const float* be2  = (const float*)d_in[17];
    float* out = (float*)d_out;

    size_t smem = (size_t)(SWROWS * HID + 2 * NDENSE * HID + 2 * NDENSE * EMBD
                           + HID + 2 * NDENSE + 8) * sizeof(float);
    cudaFuncSetAttribute(main_kernel, cudaFuncAttributeMaxDynamicSharedMemorySize, (int)smem);

    main_kernel<<<NROWS / 128, 256, smem>>>(Xi_dense, Xi_sparse, Xv, bias,
                                            T1, T2, W1d, b1d, W2d, b2d, Wl1, bl1);
    stats_kernel<<<256, 1024>>>(g1, be1, Wl2, bl2, g2, be2);
    out_kernel<<<NROWS / 256, 256>>>(out);
}